// round 15
// baseline (speedup 1.0000x reference)
#include <cuda_runtime.h>
#include <cuda_fp16.h>
#include <math.h>
#include <stdint.h>

#define BB 2
#define SS 4096
#define DM 512
#define HH 8
#define DKH 64
#define NROW (BB*SS)   // 8192

#define FQT 20   // flash smem row stride in uint4
#define GAST 12  // gemm smem row stride in uint4
#define LOG2E 1.4426950408889634f

// ---------------- scratch ---------------------------------------------------
__device__ float  g_m[BB * HH * SS];
__device__ float  g_l[BB * HH * SS];
__device__ uint4  g_inp[3ull * NROW * 128];
__device__ uint4  g_wp[4ull * 512 * 128];
__device__ uint4  g_qp[(size_t)BB * HH * SS * 16];
__device__ uint4  g_kp[(size_t)BB * HH * SS * 16];
__device__ uint4  g_vt[(size_t)BB * HH * 64 * 1024];
__device__ uint4  g_op[(size_t)BB * HH * SS * 16];
__device__ int    g_flag[512];
__device__ int    g_cnt[64];
__device__ __half g_ph[(size_t)BB * HH * SS * SS];   // fp16 partial probs
__device__ float  g_mt[(size_t)BB * HH * 64 * SS];   // running max per (bh,kt,row)

// ---------------- helpers ---------------------------------------------------
__device__ __forceinline__ float ex2(float x) {
    float y; asm("ex2.approx.ftz.f32 %0, %1;" : "=f"(y) : "f"(x)); return y;
}
__device__ __forceinline__ uint32_t bpack(float lo, float hi) {
    uint32_t r;
    asm("cvt.rn.bf16x2.f32 %0, %1, %2;" : "=r"(r) : "f"(hi), "f"(lo));
    return r;
}
__device__ __forceinline__ uint4 packsplit(float x0, float x1, float x2, float x3) {
    uint4 r;
    r.x = bpack(x0, x1);
    r.y = bpack(x2, x3);
    float h0 = __uint_as_float(r.x << 16);
    float h1 = __uint_as_float(r.x & 0xffff0000u);
    float h2 = __uint_as_float(r.y << 16);
    float h3 = __uint_as_float(r.y & 0xffff0000u);
    r.z = bpack(x0 - h0, x1 - h1);
    r.w = bpack(x2 - h2, x3 - h3);
    return r;
}
__device__ __forceinline__ void psplit(float x, float y, uint32_t& h, uint32_t& l) {
    h = bpack(x, y);
    float hx = __uint_as_float(h << 16);
    float hy = __uint_as_float(h & 0xffff0000u);
    l = bpack(x - hx, y - hy);
}
__device__ __forceinline__ void mma16(float4& c,
    uint32_t a0, uint32_t a1, uint32_t a2, uint32_t a3,
    uint32_t b0, uint32_t b1)
{
    asm volatile(
        "mma.sync.aligned.m16n8k16.row.col.f32.bf16.bf16.f32 "
        "{%0,%1,%2,%3},{%4,%5,%6,%7},{%8,%9},{%0,%1,%2,%3};"
        : "+f"(c.x), "+f"(c.y), "+f"(c.z), "+f"(c.w)
        : "r"(a0), "r"(a1), "r"(a2), "r"(a3), "r"(b0), "r"(b1));
}
__device__ __forceinline__ void cp16(uint32_t saddr, const void* gsrc) {
    asm volatile("cp.async.cg.shared.global [%0], [%1], 16;"
                 :: "r"(saddr), "l"(gsrc));
}

// ---------------------------------------------------------------------------
// packall: pack inputs+weights, clear flags.
// ---------------------------------------------------------------------------
#define NI (NROW * 32)
#define NW (512 * 32)
__global__ __launch_bounds__(256) void packall(
    const float* __restrict__ Q, const float* __restrict__ K,
    const float* __restrict__ V,
    const float* __restrict__ Wq, const float* __restrict__ Wk,
    const float* __restrict__ Wv, const float* __restrict__ Wo)
{
    if (blockIdx.x < 3) {
        int f = blockIdx.x * 256 + threadIdx.x;
        if (f < 512) g_flag[f] = 0;
        else if (f < 576) g_cnt[f - 512] = 0;
    }
    int t = blockIdx.x * 256 + threadIdx.x;
    const float* src; uint4* dst; int li;
    if (t < 3 * NI) {
        int m = t / NI; li = t - m * NI;
        src = (m == 0) ? Q : (m == 1) ? K : V;
        dst = g_inp + (size_t)m * NROW * 128;
    } else {
        int u = t - 3 * NI;
        int m = u / NW;
        if (m >= 4) return;
        li = u - m * NW;
        src = (m == 0) ? Wq : (m == 1) ? Wk : (m == 2) ? Wv : Wo;
        dst = g_wp + (size_t)m * 512 * 128;
    }
    const float* s = src + (size_t)li * 16;
    uint4* d = dst + (size_t)li * 4;
    float v[16];
    #pragma unroll
    for (int j = 0; j < 4; j++) ((float4*)v)[j] = *(const float4*)(s + j * 4);
    #pragma unroll
    for (int cc = 0; cc < 4; cc++)
        d[cc] = packsplit(v[2*cc], v[2*cc+1], v[2*cc+8], v[2*cc+9]);
}

// ---------------------------------------------------------------------------
// GEMM core: 128x64 tile, BK=32, double-buffered cp.async.
// ---------------------------------------------------------------------------
__device__ __forceinline__ void gemm_issue(
    const uint4* __restrict__ Ag, int amode, const uint4* __restrict__ Wg,
    uint32_t smA, uint32_t smW, int rowBase, int colBase, int k0, int tid)
{
    #pragma unroll
    for (int i = 0; i < 4; i++) {
        int u = tid + i * 256, row = u >> 3, q8 = u & 7;
        int grow = rowBase + row;
        size_t src;
        if (amode == 0) {
            src = (size_t)grow * 128 + (size_t)((k0 >> 4) * 4 + q8);
        } else {
            int b = grow >> 12, s = grow & (SS - 1);
            int h = k0 >> 6, ch0 = (k0 & 63) >> 4;
            src = ((size_t)(b * HH + h) * SS + s) * 16 + ch0 * 4 + q8;
        }
        cp16(smA + (row * GAST + q8) * 16, Ag + src);
    }
    #pragma unroll
    for (int i = 0; i < 2; i++) {
        int u = tid + i * 256, row = u >> 3, q8 = u & 7;
        size_t src = (size_t)(colBase + row) * 128 + (size_t)((k0 >> 4) * 4 + q8);
        cp16(smW + (row * GAST + q8) * 16, Wg + src);
    }
    asm volatile("cp.async.commit_group;");
}

__device__ __forceinline__ void gemm_core(
    const uint4* __restrict__ Ag, int amode, const uint4* __restrict__ Wg,
    const float* __restrict__ bias,
    float* __restrict__ Cf, uint4* __restrict__ Cp, float oscale,
    int vtmode, int rowBase, int colBase)
{
    extern __shared__ uint4 smu[];
    const int HB = 192 * GAST;
    uint32_t smb = (uint32_t)__cvta_generic_to_shared(smu);
    const uint4* aP[2] = { smu, smu + HB };
    const uint4* wP[2] = { smu + 128 * GAST, smu + HB + 128 * GAST };
    uint32_t aA[2] = { smb, smb + (uint32_t)HB * 16 };
    uint32_t wA[2] = { smb + 128 * GAST * 16, smb + (uint32_t)HB * 16 + 128 * GAST * 16 };

    const int tid = threadIdx.x, lane = tid & 31, w = tid >> 5;
    const int r0 = lane >> 2, c4 = lane & 3;
    const int m0 = w * 16;

    float4 acc[8];
    #pragma unroll
    for (int i = 0; i < 8; i++) acc[i] = make_float4(0.f, 0.f, 0.f, 0.f);

    gemm_issue(Ag, amode, Wg, aA[0], wA[0], rowBase, colBase, 0, tid);
    int buf = 0;
    for (int k0 = 0; k0 < DM; k0 += 32) {
        asm volatile("cp.async.wait_group 0;");
        __syncthreads();
        if (k0 + 32 < DM)
            gemm_issue(Ag, amode, Wg, aA[buf ^ 1], wA[buf ^ 1],
                       rowBase, colBase, k0 + 32, tid);
        const uint4* Ap = aP[buf];
        const uint4* Wp = wP[buf];
        #pragma unroll
        for (int ch = 0; ch < 2; ch++) {
            uint4 aa = Ap[(m0 + r0) * GAST + ch * 4 + c4];
            uint4 ab = Ap[(m0 + r0 + 8) * GAST + ch * 4 + c4];
            #pragma unroll
            for (int nf = 0; nf < 8; nf++) {
                uint4 wv = Wp[(nf * 8 + r0) * GAST + ch * 4 + c4];
                mma16(acc[nf], aa.x, ab.x, aa.y, ab.y, wv.x, wv.y);
                mma16(acc[nf], aa.x, ab.x, aa.y, ab.y, wv.z, wv.w);
                mma16(acc[nf], aa.z, ab.z, aa.w, ab.w, wv.x, wv.y);
            }
        }
        buf ^= 1;
    }

    int r = rowBase + m0 + r0;
    if (vtmode) {
        float* sv = (float*)smu;
        __syncthreads();
        #pragma unroll
        for (int nf = 0; nf < 8; nf++) {
            int col = nf * 8 + 2 * c4;
            float bx = bias[colBase + col], by = bias[colBase + col + 1];
            *(float2*)&sv[(m0 + r0) * 68 + col] =
                make_float2(acc[nf].x + bx, acc[nf].y + by);
            *(float2*)&sv[(m0 + r0 + 8) * 68 + col] =
                make_float2(acc[nf].z + bx, acc[nf].w + by);
        }
        __syncthreads();
        int d = tid & 63, g = tid >> 6;
        int b = rowBase >> 12;
        int bh = b * HH + (colBase >> 6);
        int gbase = (rowBase & (SS - 1)) >> 4;
        uint4* dst = g_vt + ((size_t)(bh * 64 + d) << 10);
        #pragma unroll
        for (int i = 0; i < 2; i++) {
            int gg = g + 4 * i;
            #pragma unroll
            for (int cc = 0; cc < 4; cc++) {
                int t0 = 16 * gg + 2 * cc;
                dst[(gbase + gg) * 4 + cc] = packsplit(
                    sv[t0 * 68 + d], sv[(t0 + 1) * 68 + d],
                    sv[(t0 + 8) * 68 + d], sv[(t0 + 9) * 68 + d]);
            }
        }
    } else if (Cp) {
        int h = colBase >> 6;
        int b = r >> 12, s = r & (SS - 1);
        size_t ro0 = ((size_t)(b * HH + h) * SS + s) * 16;
        size_t ro1 = ro0 + 8 * 16;
        #pragma unroll
        for (int ch = 0; ch < 4; ch++) {
            int col = colBase + ch * 16 + 2 * c4;
            float b0 = bias[col],     b1 = bias[col + 1];
            float b8 = bias[col + 8], b9 = bias[col + 9];
            Cp[ro0 + ch * 4 + c4] = packsplit(
                (acc[2*ch].x + b0) * oscale, (acc[2*ch].y + b1) * oscale,
                (acc[2*ch+1].x + b8) * oscale, (acc[2*ch+1].y + b9) * oscale);
            Cp[ro1 + ch * 4 + c4] = packsplit(
                (acc[2*ch].z + b0) * oscale, (acc[2*ch].w + b1) * oscale,
                (acc[2*ch+1].z + b8) * oscale, (acc[2*ch+1].w + b9) * oscale);
        }
    } else {
        #pragma unroll
        for (int nf = 0; nf < 8; nf++) {
            int col = colBase + nf * 8 + 2 * c4;
            float bx = bias[col], by = bias[col + 1];
            *(float2*)&Cf[(size_t)r * DM + col] =
                make_float2(acc[nf].x + bx, acc[nf].y + by);
            *(float2*)&Cf[(size_t)(r + 8) * DM + col] =
                make_float2(acc[nf].z + bx, acc[nf].w + by);
        }
    }
}

// Projections kernel (separate launch, as in the best-known config)
__global__ __launch_bounds__(256, 2) void gemm_proj(
    const float* __restrict__ bq, const float* __restrict__ bk,
    const float* __restrict__ bv)
{
    int z = blockIdx.z;
    const uint4* Ag = g_inp + (size_t)z * NROW * 128;
    const uint4* Wg = g_wp + (size_t)z * 512 * 128;
    int rb = blockIdx.y * 128, cb = blockIdx.x * 64;
    if (z == 0)
        gemm_core(Ag, 0, Wg, bq, nullptr, g_qp, 0.125f * LOG2E, 0, rb, cb);
    else if (z == 1)
        gemm_core(Ag, 0, Wg, bk, nullptr, g_kp, 1.f, 0, rb, cb);
    else
        gemm_core(Ag, 0, Wg, bv, nullptr, nullptr, 1.f, 1, rb, cb);
}

// ---------------------------------------------------------------------------
// Flash block: optionally streams fp16 partial probs + running-max table.
// ---------------------------------------------------------------------------
__device__ __forceinline__ void kv_issue(uint32_t smK, uint32_t smV,
                                         int bh, int kbase, int tid)
{
    #pragma unroll
    for (int i = 0; i < 4; i++) {
        int u = tid + i * 256, row = u >> 4, q = u & 15;
        cp16(smK + (row * FQT + q) * 16,
             g_kp + ((size_t)bh * SS + kbase + row) * 16 + q);
    }
    #pragma unroll
    for (int i = 0; i < 4; i++) {
        int u = tid + i * 256, d = u >> 4, q = u & 15;
        cp16(smV + (d * FQT + q) * 16,
             g_vt + (((size_t)(bh * 64 + d)) << 10) + (kbase >> 4) * 4 + q);
    }
    asm volatile("cp.async.commit_group;");
}

__device__ __forceinline__ void flash_dev(int fi, int store_p)
{
    extern __shared__ uint4 smf[];
    const int tid = threadIdx.x;
    const int KB = 64 * FQT;
    uint32_t smb = (uint32_t)__cvta_generic_to_shared(smf);
    const uint4* Kb[2] = { smf, smf + 2 * KB };
    const uint4* Vb[2] = { smf + KB, smf + 3 * KB };
    uint32_t Ka[2] = { smb, smb + (uint32_t)(2 * KB) * 16 };
    uint32_t Va[2] = { smb + (uint32_t)KB * 16, smb + (uint32_t)(3 * KB) * 16 };

    const int lane = tid & 31, w = tid >> 5;
    const int r0 = lane >> 2, c4 = lane & 3;
    const int qt = 31 - (fi >> 4);
    const int bh = fi & 15;
    const int qbase = qt * 128;
    const int wrow = qbase + w * 16;
    const int ri0 = wrow + r0, ri1 = ri0 + 8;
    const size_t prow0 = (size_t)bh * SS + ri0;
    const size_t prow1 = (size_t)bh * SS + ri1;

    kv_issue(Ka[0], Va[0], bh, 0, tid);

    uint4 qa[4], qb[4];
    {
        size_t q0 = ((size_t)bh * SS + ri0) * 16;
        size_t q1 = ((size_t)bh * SS + ri1) * 16;
        #pragma unroll
        for (int ch = 0; ch < 4; ch++) {
            qa[ch] = g_qp[q0 + ch * 4 + c4];
            qb[ch] = g_qp[q1 + ch * 4 + c4];
        }
    }

    float4 o[8];
    #pragma unroll
    for (int i = 0; i < 8; i++) o[i] = make_float4(0.f, 0.f, 0.f, 0.f);
    float m0v = -1e30f, m1v = -1e30f, l0v = 0.f, l1v = 0.f;

    int buf = 0;
    const int ktmax = 2 * qt + 1;
    for (int kt = 0; kt <= ktmax; kt++) {
        const int kbase = kt << 6;
        asm volatile("cp.async.wait_group 0;");
        __syncthreads();
        if (kt < ktmax) kv_issue(Ka[buf ^ 1], Va[buf ^ 1], bh, (kt + 1) << 6, tid);

        if (kbase <= wrow + 15) {
            const uint4* Kp = Kb[buf];
            const uint4* Vp = Vb[buf];
            float4 s[8];
            #pragma unroll
            for (int i = 0; i < 8; i++) s[i] = make_float4(0.f, 0.f, 0.f, 0.f);

            #pragma unroll
            for (int ch = 0; ch < 4; ch++) {
                #pragma unroll
                for (int nf = 0; nf < 8; nf++) {
                    uint4 kv = Kp[(nf * 8 + r0) * FQT + ch * 4 + c4];
                    mma16(s[nf], qa[ch].x, qb[ch].x, qa[ch].y, qb[ch].y, kv.x, kv.y);
                    mma16(s[nf], qa[ch].x, qb[ch].x, qa[ch].y, qb[ch].y, kv.z, kv.w);
                    mma16(s[nf], qa[ch].z, qb[ch].z, qa[ch].w, qb[ch].w, kv.x, kv.y);
                }
            }

            if (kbase + 63 > wrow) {
                #pragma unroll
                for (int nf = 0; nf < 8; nf++) {
                    int j0 = kbase + nf * 8 + 2 * c4;
                    if (j0     > ri0) s[nf].x = -INFINITY;
                    if (j0 + 1 > ri0) s[nf].y = -INFINITY;
                    if (j0     > ri1) s[nf].z = -INFINITY;
                    if (j0 + 1 > ri1) s[nf].w = -INFINITY;
                }
            }

            float mt0 = -1e30f, mt1 = -1e30f;
            #pragma unroll
            for (int nf = 0; nf < 8; nf++) {
                mt0 = fmaxf(mt0, fmaxf(s[nf].x, s[nf].y));
                mt1 = fmaxf(mt1, fmaxf(s[nf].z, s[nf].w));
            }
            mt0 = fmaxf(mt0, __shfl_xor_sync(0xffffffffu, mt0, 1));
            mt0 = fmaxf(mt0, __shfl_xor_sync(0xffffffffu, mt0, 2));
            mt1 = fmaxf(mt1, __shfl_xor_sync(0xffffffffu, mt1, 1));
            mt1 = fmaxf(mt1, __shfl_xor_sync(0xffffffffu, mt1, 2));
            float mn0 = fmaxf(m0v, mt0), mn1 = fmaxf(m1v, mt1);
            float al0 = ex2(m0v - mn0), al1 = ex2(m1v - mn1);
            m0v = mn0; m1v = mn1; l0v *= al0; l1v *= al1;

            float rs0 = 0.f, rs1 = 0.f;
            #pragma unroll
            for (int nf = 0; nf < 8; nf++) {
                s[nf].x = ex2(s[nf].x - mn0);
                s[nf].y = ex2(s[nf].y - mn0);
                s[nf].z = ex2(s[nf].z - mn1);
                s[nf].w = ex2(s[nf].w - mn1);
                rs0 += s[nf].x + s[nf].y;
                rs1 += s[nf].z + s[nf].w;
                o[nf].x *= al0; o[nf].y *= al0;
                o[nf].z *= al1; o[nf].w *= al1;
            }
            rs0 += __shfl_xor_sync(0xffffffffu, rs0, 1);
            rs0 += __shfl_xor_sync(0xffffffffu, rs0, 2);
            rs1 += __shfl_xor_sync(0xffffffffu, rs1, 1);
            rs1 += __shfl_xor_sync(0xffffffffu, rs1, 2);
            l0v += rs0; l1v += rs1;

            if (store_p) {
                #pragma unroll
                for (int nf = 0; nf < 8; nf++) {
                    int col = kbase + nf * 8 + 2 * c4;
                    __half2 h0 = __floats2half2_rn(s[nf].x, s[nf].y);
                    __half2 h1 = __floats2half2_rn(s[nf].z, s[nf].w);
                    __stcs((__half2*)&g_ph[prow0 * SS + col], h0);
                    __stcs((__half2*)&g_ph[prow1 * SS + col], h1);
                }
                if (c4 == 0) {
                    size_t mb = ((size_t)(bh * 64 + kt)) << 12;
                    g_mt[mb + ri0] = mn0;
                    g_mt[mb + ri1] = mn1;
                }
            }

            #pragma unroll
            for (int ch = 0; ch < 4; ch++) {
                int n0 = 2 * ch, n1 = n0 + 1;
                uint32_t a0h, a0l, a1h, a1l, a2h, a2l, a3h, a3l;
                psplit(s[n0].x, s[n0].y, a0h, a0l);
                psplit(s[n0].z, s[n0].w, a1h, a1l);
                psplit(s[n1].x, s[n1].y, a2h, a2l);
                psplit(s[n1].z, s[n1].w, a3h, a3l);
                #pragma unroll
                for (int nf = 0; nf < 8; nf++) {
                    uint4 vv = Vp[(nf * 8 + r0) * FQT + ch * 4 + c4];
                    mma16(o[nf], a0h, a1h, a2h, a3h, vv.x, vv.y);
                    mma16(o[nf], a0h, a1h, a2h, a3h, vv.z, vv.w);
                    mma16(o[nf], a0l, a1l, a2l, a3l, vv.x, vv.y);
                }
            }
        }
        buf ^= 1;
    }

    float inv0 = 1.f / l0v, inv1 = 1.f / l1v;
    size_t ro0 = ((size_t)bh * SS + ri0) * 16;
    size_t ro1 = ((size_t)bh * SS + ri1) * 16;
    #pragma unroll
    for (int ch = 0; ch < 4; ch++) {
        g_op[ro0 + ch * 4 + c4] = packsplit(
            o[2*ch].x * inv0, o[2*ch].y * inv0,
            o[2*ch+1].x * inv0, o[2*ch+1].y * inv0);
        g_op[ro1 + ch * 4 + c4] = packsplit(
            o[2*ch].z * inv1, o[2*ch].w * inv1,
            o[2*ch+1].z * inv1, o[2*ch+1].w * inv1);
    }
    if (c4 == 0) {
        g_m[bh * SS + ri0] = m0v; g_m[bh * SS + ri1] = m1v;
        g_l[bh * SS + ri0] = l0v; g_l[bh * SS + ri1] = l1v;
    }

    __threadfence();
    __syncthreads();
    if (tid == 0) {
        atomicExch(&g_flag[fi], 1);
        atomicAdd(&g_cnt[(bh >> 3) * 32 + qt], 1);
    }
}

// ---------------------------------------------------------------------------
// fin: attn = p_fp16 * ex2(m_kt - m_fin) / l, in the causal band; j>i -> 0.
// ---------------------------------------------------------------------------
__device__ __forceinline__ void fin_dev(float* __restrict__ attn, int idx)
{
    extern __shared__ uint4 sme[];
    float* sc = (float*)sme;                 // [128][66] scale table

    const int tid = threadIdx.x;
    const int qt = 31 - (idx >> 4);
    const int bh = idx & 15;
    const int qbase = qt * 128;
    const int ntile = 2 * qt + 2;

    if (tid == 0) {
        while (atomicAdd(&g_flag[idx], 0) == 0) __nanosleep(200);
    }
    __syncthreads();
    __threadfence();

    for (int f = tid; f < 128 * ntile; f += 256) {
        int r = f / ntile, kt = f - r * ntile;
        int row = qbase + r;
        float mfin = g_m[bh * SS + row];
        float invl = 1.f / g_l[bh * SS + row];
        sc[r * 66 + kt] =
            ex2(g_mt[(((size_t)(bh * 64 + kt)) << 12) + row] - mfin) * invl;
    }
    __syncthreads();

    const int nc = ntile << 4;              // float4 chunks per row
    for (int r = 0; r < 128; r++) {
        int row = qbase + r;
        size_t base = ((size_t)bh * SS + row) * (size_t)SS;
        const __half* ph = g_ph + base;
        float* ap = attn + base;
        const float* scr = sc + r * 66;
        for (int c = tid; c < nc; c += 256) {
            int j0 = c << 2;
            float s = scr[c >> 4];
            uint2 u = *(const uint2*)(ph + j0);
            float2 f0 = __half22float2(*(__half2*)&u.x);
            float2 f1 = __half22float2(*(__half2*)&u.y);
            float4 o;
            o.x = (j0     <= row) ? f0.x * s : 0.f;
            o.y = (j0 + 1 <= row) ? f0.y * s : 0.f;
            o.z = (j0 + 2 <= row) ? f1.x * s : 0.f;
            o.w = (j0 + 3 <= row) ? f1.y * s : 0.f;
            __stcs((float4*)(ap + j0), o);
        }
    }
}

// ---------------------------------------------------------------------------
// Fused tail: [flash/zero interleaved] then [fin/out-proj interleaved].
// ---------------------------------------------------------------------------
__global__ __launch_bounds__(256, 2) void fused_tail(
    float* __restrict__ attn, const float* __restrict__ bo,
    float* __restrict__ out, int nFlash, int nAttn, int nGemm)
{
    const int bid = blockIdx.x;
    const int tid = threadIdx.x;

    if (bid < nFlash) {
        if (attn) {
            if (bid & 1) {
                int zi = bid >> 1;
                int zqt = zi >> 4, zbh = zi & 15;
                int z0 = (2 * zqt + 2) * 64;
                int cw = (SS - z0) >> 2;
                if (cw > 0) {
                    float4 z = make_float4(0.f, 0.f, 0.f, 0.f);
                    int zqbase = zqt * 128;
                    for (int r = 0; r < 128; r++) {
                        float* rowp = attn +
                            ((size_t)zbh * SS + zqbase + r) * SS + z0;
                        for (int c = tid; c < cw; c += 256)
                            __stcs((float4*)&rowp[4 * c], z);
                    }
                }
                return;
            }
            flash_dev(bid >> 1, 1);
        } else {
            flash_dev(bid, 0);
        }
        return;
    }

    int idx = bid - nFlash;
    int aidx = -1, gidx = -1;
    if (nAttn && nGemm) {
        if (idx & 1) gidx = idx >> 1; else aidx = idx >> 1;
    } else if (nAttn) aidx = idx;
    else gidx = idx;

    if (aidx >= 0) {
        fin_dev(attn, aidx);
    } else {
        int rowBase = (gidx >> 3) * 128;
        int b = rowBase >> 12, qt = (rowBase & (SS - 1)) >> 7;
        if (tid == 0) {
            while (atomicAdd(&g_cnt[b * 32 + qt], 0) < HH) __nanosleep(200);
        }
        __syncthreads();
        __threadfence();
        gemm_core(g_op, 1, g_wp + 3ull * 512 * 128, bo, out, nullptr, 1.f, 0,
                  rowBase, (gidx & 7) * 64);
    }
}

// ---------------------------------------------------------------------------
extern "C" void kernel_launch(void* const* d_in, const int* in_sizes, int n_in,
                              void* d_out, int out_size)
{
    const float* Q  = (const float*)d_in[0];
    const float* Kx = (const float*)d_in[1];
    const float* V  = (const float*)d_in[2];
    const float* Wq = (const float*)d_in[3];
    const float* bq = (const float*)d_in[4];
    const float* Wk = (const float*)d_in[5];
    const float* bk = (const float*)d_in[6];
    const float* Wv = (const float*)d_in[7];
    const float* bv = (const float*)d_in[8];
    const float* Wo = (const float*)d_in[9];
    const float* bo = (const float*)d_in[10];
    float* out = (float*)d_out;

    const int GEMM_SMEM = 2 * 192 * GAST * 16;   // 73728
    const int TAIL_SMEM = 4 * 64 * FQT * 16;     // 81920
    cudaFuncSetAttribute(gemm_proj, cudaFuncAttributeMaxDynamicSharedMemorySize,
                         GEMM_SMEM);
    cudaFuncSetAttribute(fused_tail, cudaFuncAttributeMaxDynamicSharedMemorySize,
                         TAIL_SMEM);

    packall<<<(3 * NI + 4 * NW + 255) / 256, 256>>>(Q, Kx, V, Wq, Wk, Wv, Wo);

    gemm_proj<<<dim3(DM / 64, NROW / 128, 3), 256, GEMM_SMEM>>>(bq, bk, bv);

    const long long OUTN = (long long)NROW * DM;
    const long long ATTN = (long long)BB * HH * SS * (long long)SS;
    float* out_ptr = out;
    float* attn_ptr = nullptr;
    if ((long long)out_size == ATTN) { attn_ptr = out; out_ptr = nullptr; }
    else if ((long long)out_size >= OUTN + ATTN) attn_ptr = out + OUTN;

    int nFlash = attn_ptr ? 1024 : 512;
    int nAttn  = attn_ptr ? 512 : 0;
    int nGemm  = out_ptr ? 512 : 0;
    fused_tail<<<nFlash + nAttn + nGemm, 256, TAIL_SMEM>>>(
        attn_ptr, bo, out_ptr, nFlash, nAttn, nGemm);
}

// round 16
// speedup vs baseline: 1.4128x; 1.4128x over previous
#include <cuda_runtime.h>
#include <math.h>
#include <stdint.h>

#define BB 2
#define SS 4096
#define DM 512
#define HH 8
#define DKH 64
#define NROW (BB*SS)   // 8192

#define FQT 20
#define GAST 12
#define LOG2E 1.4426950408889634f

// ---------------- scratch ---------------------------------------------------
__device__ float g_m[BB * HH * SS];
__device__ float g_l[BB * HH * SS];
__device__ uint4 g_inp[3ull * NROW * 128];
__device__ uint4 g_wp[4ull * 512 * 128];
__device__ uint4 g_qp[(size_t)BB * HH * SS * 16];
__device__ uint4 g_kp[(size_t)BB * HH * SS * 16];
__device__ uint4 g_vt[(size_t)BB * HH * 64 * 1024];
__device__ uint4 g_op[(size_t)BB * HH * SS * 16];
__device__ int   g_flag[512];    // per-(qt,bh) flash done
__device__ int   g_cnt[64];      // per-(b,qt) flash done count
__device__ int   g_pflag[1536];  // per-(z,bh,chunk) proj done

// ---------------- helpers ---------------------------------------------------
__device__ __forceinline__ float ex2(float x) {
    float y; asm("ex2.approx.ftz.f32 %0, %1;" : "=f"(y) : "f"(x)); return y;
}
__device__ __forceinline__ uint32_t bpack(float lo, float hi) {
    uint32_t r;
    asm("cvt.rn.bf16x2.f32 %0, %1, %2;" : "=r"(r) : "f"(hi), "f"(lo));
    return r;
}
__device__ __forceinline__ uint4 packsplit(float x0, float x1, float x2, float x3) {
    uint4 r;
    r.x = bpack(x0, x1);
    r.y = bpack(x2, x3);
    float h0 = __uint_as_float(r.x << 16);
    float h1 = __uint_as_float(r.x & 0xffff0000u);
    float h2 = __uint_as_float(r.y << 16);
    float h3 = __uint_as_float(r.y & 0xffff0000u);
    r.z = bpack(x0 - h0, x1 - h1);
    r.w = bpack(x2 - h2, x3 - h3);
    return r;
}
__device__ __forceinline__ void psplit(float x, float y, uint32_t& h, uint32_t& l) {
    h = bpack(x, y);
    float hx = __uint_as_float(h << 16);
    float hy = __uint_as_float(h & 0xffff0000u);
    l = bpack(x - hx, y - hy);
}
__device__ __forceinline__ void mma16(float4& c,
    uint32_t a0, uint32_t a1, uint32_t a2, uint32_t a3,
    uint32_t b0, uint32_t b1)
{
    asm volatile(
        "mma.sync.aligned.m16n8k16.row.col.f32.bf16.bf16.f32 "
        "{%0,%1,%2,%3},{%4,%5,%6,%7},{%8,%9},{%0,%1,%2,%3};"
        : "+f"(c.x), "+f"(c.y), "+f"(c.z), "+f"(c.w)
        : "r"(a0), "r"(a1), "r"(a2), "r"(a3), "r"(b0), "r"(b1));
}
__device__ __forceinline__ void cp16(uint32_t saddr, const void* gsrc) {
    asm volatile("cp.async.cg.shared.global [%0], [%1], 16;"
                 :: "r"(saddr), "l"(gsrc));
}

// ---------------------------------------------------------------------------
// packall: pack inputs+weights, clear all flags.
// ---------------------------------------------------------------------------
#define NI (NROW * 32)
#define NW (512 * 32)
__global__ __launch_bounds__(256) void packall(
    const float* __restrict__ Q, const float* __restrict__ K,
    const float* __restrict__ V,
    const float* __restrict__ Wq, const float* __restrict__ Wk,
    const float* __restrict__ Wv, const float* __restrict__ Wo)
{
    if (blockIdx.x < 9) {
        int f = blockIdx.x * 256 + threadIdx.x;
        if (f < 1536) g_pflag[f] = 0;
        else if (f < 2048) g_flag[f - 1536] = 0;
        else if (f < 2112) g_cnt[f - 2048] = 0;
    }
    int t = blockIdx.x * 256 + threadIdx.x;
    const float* src; uint4* dst; int li;
    if (t < 3 * NI) {
        int m = t / NI; li = t - m * NI;
        src = (m == 0) ? Q : (m == 1) ? K : V;
        dst = g_inp + (size_t)m * NROW * 128;
    } else {
        int u = t - 3 * NI;
        int m = u / NW;
        if (m >= 4) return;
        li = u - m * NW;
        src = (m == 0) ? Wq : (m == 1) ? Wk : (m == 2) ? Wv : Wo;
        dst = g_wp + (size_t)m * 512 * 128;
    }
    const float* s = src + (size_t)li * 16;
    uint4* d = dst + (size_t)li * 4;
    float v[16];
    #pragma unroll
    for (int j = 0; j < 4; j++) ((float4*)v)[j] = *(const float4*)(s + j * 4);
    #pragma unroll
    for (int cc = 0; cc < 4; cc++)
        d[cc] = packsplit(v[2*cc], v[2*cc+1], v[2*cc+8], v[2*cc+9]);
}

// ---------------------------------------------------------------------------
// GEMM core: 128x64 tile, BK=32, double-buffered cp.async.
// ---------------------------------------------------------------------------
__device__ __forceinline__ void gemm_issue(
    const uint4* __restrict__ Ag, int amode, const uint4* __restrict__ Wg,
    uint32_t smA, uint32_t smW, int rowBase, int colBase, int k0, int tid)
{
    #pragma unroll
    for (int i = 0; i < 4; i++) {
        int u = tid + i * 256, row = u >> 3, q8 = u & 7;
        int grow = rowBase + row;
        size_t src;
        if (amode == 0) {
            src = (size_t)grow * 128 + (size_t)((k0 >> 4) * 4 + q8);
        } else {
            int b = grow >> 12, s = grow & (SS - 1);
            int h = k0 >> 6, ch0 = (k0 & 63) >> 4;
            src = ((size_t)(b * HH + h) * SS + s) * 16 + ch0 * 4 + q8;
        }
        cp16(smA + (row * GAST + q8) * 16, Ag + src);
    }
    #pragma unroll
    for (int i = 0; i < 2; i++) {
        int u = tid + i * 256, row = u >> 3, q8 = u & 7;
        size_t src = (size_t)(colBase + row) * 128 + (size_t)((k0 >> 4) * 4 + q8);
        cp16(smW + (row * GAST + q8) * 16, Wg + src);
    }
    asm volatile("cp.async.commit_group;");
}

__device__ __forceinline__ void gemm_core(
    const uint4* __restrict__ Ag, int amode, const uint4* __restrict__ Wg,
    const float* __restrict__ bias,
    float* __restrict__ Cf, uint4* __restrict__ Cp, float oscale,
    int vtmode, int rowBase, int colBase)
{
    extern __shared__ uint4 smu[];
    const int HB = 192 * GAST;
    uint32_t smb = (uint32_t)__cvta_generic_to_shared(smu);
    const uint4* aP[2] = { smu, smu + HB };
    const uint4* wP[2] = { smu + 128 * GAST, smu + HB + 128 * GAST };
    uint32_t aA[2] = { smb, smb + (uint32_t)HB * 16 };
    uint32_t wA[2] = { smb + 128 * GAST * 16, smb + (uint32_t)HB * 16 + 128 * GAST * 16 };

    const int tid = threadIdx.x, lane = tid & 31, w = tid >> 5;
    const int r0 = lane >> 2, c4 = lane & 3;
    const int m0 = w * 16;

    float4 acc[8];
    #pragma unroll
    for (int i = 0; i < 8; i++) acc[i] = make_float4(0.f, 0.f, 0.f, 0.f);

    gemm_issue(Ag, amode, Wg, aA[0], wA[0], rowBase, colBase, 0, tid);
    int buf = 0;
    for (int k0 = 0; k0 < DM; k0 += 32) {
        asm volatile("cp.async.wait_group 0;");
        __syncthreads();
        if (k0 + 32 < DM)
            gemm_issue(Ag, amode, Wg, aA[buf ^ 1], wA[buf ^ 1],
                       rowBase, colBase, k0 + 32, tid);
        const uint4* Ap = aP[buf];
        const uint4* Wp = wP[buf];
        #pragma unroll
        for (int ch = 0; ch < 2; ch++) {
            uint4 aa = Ap[(m0 + r0) * GAST + ch * 4 + c4];
            uint4 ab = Ap[(m0 + r0 + 8) * GAST + ch * 4 + c4];
            #pragma unroll
            for (int nf = 0; nf < 8; nf++) {
                uint4 wv = Wp[(nf * 8 + r0) * GAST + ch * 4 + c4];
                mma16(acc[nf], aa.x, ab.x, aa.y, ab.y, wv.x, wv.y);
                mma16(acc[nf], aa.x, ab.x, aa.y, ab.y, wv.z, wv.w);
                mma16(acc[nf], aa.z, ab.z, aa.w, ab.w, wv.x, wv.y);
            }
        }
        buf ^= 1;
    }

    int r = rowBase + m0 + r0;
    if (vtmode) {
        float* sv = (float*)smu;
        __syncthreads();
        #pragma unroll
        for (int nf = 0; nf < 8; nf++) {
            int col = nf * 8 + 2 * c4;
            float bx = bias[colBase + col], by = bias[colBase + col + 1];
            *(float2*)&sv[(m0 + r0) * 68 + col] =
                make_float2(acc[nf].x + bx, acc[nf].y + by);
            *(float2*)&sv[(m0 + r0 + 8) * 68 + col] =
                make_float2(acc[nf].z + bx, acc[nf].w + by);
        }
        __syncthreads();
        int d = tid & 63, g = tid >> 6;
        int b = rowBase >> 12;
        int bh = b * HH + (colBase >> 6);
        int gbase = (rowBase & (SS - 1)) >> 4;
        uint4* dst = g_vt + ((size_t)(bh * 64 + d) << 10);
        #pragma unroll
        for (int i = 0; i < 2; i++) {
            int gg = g + 4 * i;
            #pragma unroll
            for (int cc = 0; cc < 4; cc++) {
                int t0 = 16 * gg + 2 * cc;
                dst[(gbase + gg) * 4 + cc] = packsplit(
                    sv[t0 * 68 + d], sv[(t0 + 1) * 68 + d],
                    sv[(t0 + 8) * 68 + d], sv[(t0 + 9) * 68 + d]);
            }
        }
    } else if (Cp) {
        int h = colBase >> 6;
        int b = r >> 12, s = r & (SS - 1);
        size_t ro0 = ((size_t)(b * HH + h) * SS + s) * 16;
        size_t ro1 = ro0 + 8 * 16;
        #pragma unroll
        for (int ch = 0; ch < 4; ch++) {
            int col = colBase + ch * 16 + 2 * c4;
            float b0 = bias[col],     b1 = bias[col + 1];
            float b8 = bias[col + 8], b9 = bias[col + 9];
            Cp[ro0 + ch * 4 + c4] = packsplit(
                (acc[2*ch].x + b0) * oscale, (acc[2*ch].y + b1) * oscale,
                (acc[2*ch+1].x + b8) * oscale, (acc[2*ch+1].y + b9) * oscale);
            Cp[ro1 + ch * 4 + c4] = packsplit(
                (acc[2*ch].z + b0) * oscale, (acc[2*ch].w + b1) * oscale,
                (acc[2*ch+1].z + b8) * oscale, (acc[2*ch+1].w + b9) * oscale);
        }
    } else {
        #pragma unroll
        for (int nf = 0; nf < 8; nf++) {
            int col = colBase + nf * 8 + 2 * c4;
            float bx = bias[col], by = bias[col + 1];
            *(float2*)&Cf[(size_t)r * DM + col] =
                make_float2(acc[nf].x + bx, acc[nf].y + by);
            *(float2*)&Cf[(size_t)(r + 8) * DM + col] =
                make_float2(acc[nf].z + bx, acc[nf].w + by);
        }
    }
}

// ---------------------------------------------------------------------------
// Flash block (device fn); waits on proj flags, signals completion.
// ---------------------------------------------------------------------------
__device__ __forceinline__ void kv_issue(uint32_t smK, uint32_t smV,
                                         int bh, int kbase, int tid)
{
    #pragma unroll
    for (int i = 0; i < 4; i++) {
        int u = tid + i * 256, row = u >> 4, q = u & 15;
        cp16(smK + (row * FQT + q) * 16,
             g_kp + ((size_t)bh * SS + kbase + row) * 16 + q);
    }
    #pragma unroll
    for (int i = 0; i < 4; i++) {
        int u = tid + i * 256, d = u >> 4, q = u & 15;
        cp16(smV + (d * FQT + q) * 16,
             g_vt + (((size_t)(bh * 64 + d)) << 10) + (kbase >> 4) * 4 + q);
    }
    asm volatile("cp.async.commit_group;");
}

__device__ __forceinline__ void flash_dev(int fi)
{
    extern __shared__ uint4 smf[];
    const int tid = threadIdx.x;
    const int lane = tid & 31, w = tid >> 5;
    const int r0 = lane >> 2, c4 = lane & 3;
    const int qt = 31 - (fi >> 4);
    const int bh = fi & 15;
    const int qbase = qt * 128;
    const int wrow = qbase + w * 16;
    const int ri0 = wrow + r0, ri1 = ri0 + 8;

    // wait for projection flags: q chunk qt; k,v chunks 0..qt (this bh)
    {
        const int need = 2 * (qt + 1) + 1;
        for (;;) {
            bool ok = true;
            for (int f = tid; f < need; f += 256) {
                int z, c;
                if (f == 0) { z = 0; c = qt; }
                else if (f <= qt + 1) { z = 1; c = f - 1; }
                else { z = 2; c = f - qt - 2; }
                if (atomicAdd(&g_pflag[z * 512 + bh * 32 + c], 0) == 0)
                    ok = false;
            }
            if (__syncthreads_and(ok)) break;
            __nanosleep(200);
        }
        __threadfence();
    }

    const int KB = 64 * FQT;
    uint32_t smb = (uint32_t)__cvta_generic_to_shared(smf);
    const uint4* Kb[2] = { smf, smf + 2 * KB };
    const uint4* Vb[2] = { smf + KB, smf + 3 * KB };
    uint32_t Ka[2] = { smb, smb + (uint32_t)(2 * KB) * 16 };
    uint32_t Va[2] = { smb + (uint32_t)KB * 16, smb + (uint32_t)(3 * KB) * 16 };

    kv_issue(Ka[0], Va[0], bh, 0, tid);

    uint4 qa[4], qb[4];
    {
        size_t q0 = ((size_t)bh * SS + ri0) * 16;
        size_t q1 = ((size_t)bh * SS + ri1) * 16;
        #pragma unroll
        for (int ch = 0; ch < 4; ch++) {
            qa[ch] = g_qp[q0 + ch * 4 + c4];
            qb[ch] = g_qp[q1 + ch * 4 + c4];
        }
    }

    float4 o[8];
    #pragma unroll
    for (int i = 0; i < 8; i++) o[i] = make_float4(0.f, 0.f, 0.f, 0.f);
    float m0v = -1e30f, m1v = -1e30f, l0v = 0.f, l1v = 0.f;

    int buf = 0;
    const int ktmax = 2 * qt + 1;
    for (int kt = 0; kt <= ktmax; kt++) {
        const int kbase = kt << 6;
        asm volatile("cp.async.wait_group 0;");
        __syncthreads();
        if (kt < ktmax) kv_issue(Ka[buf ^ 1], Va[buf ^ 1], bh, (kt + 1) << 6, tid);

        if (kbase <= wrow + 15) {
            const uint4* Kp = Kb[buf];
            const uint4* Vp = Vb[buf];
            float4 s[8];
            #pragma unroll
            for (int i = 0; i < 8; i++) s[i] = make_float4(0.f, 0.f, 0.f, 0.f);

            #pragma unroll
            for (int ch = 0; ch < 4; ch++) {
                #pragma unroll
                for (int nf = 0; nf < 8; nf++) {
                    uint4 kv = Kp[(nf * 8 + r0) * FQT + ch * 4 + c4];
                    mma16(s[nf], qa[ch].x, qb[ch].x, qa[ch].y, qb[ch].y, kv.x, kv.y);
                    mma16(s[nf], qa[ch].x, qb[ch].x, qa[ch].y, qb[ch].y, kv.z, kv.w);
                    mma16(s[nf], qa[ch].z, qb[ch].z, qa[ch].w, qb[ch].w, kv.x, kv.y);
                }
            }

            if (kbase + 63 > wrow) {
                #pragma unroll
                for (int nf = 0; nf < 8; nf++) {
                    int j0 = kbase + nf * 8 + 2 * c4;
                    if (j0     > ri0) s[nf].x = -INFINITY;
                    if (j0 + 1 > ri0) s[nf].y = -INFINITY;
                    if (j0     > ri1) s[nf].z = -INFINITY;
                    if (j0 + 1 > ri1) s[nf].w = -INFINITY;
                }
            }

            float mt0 = -1e30f, mt1 = -1e30f;
            #pragma unroll
            for (int nf = 0; nf < 8; nf++) {
                mt0 = fmaxf(mt0, fmaxf(s[nf].x, s[nf].y));
                mt1 = fmaxf(mt1, fmaxf(s[nf].z, s[nf].w));
            }
            mt0 = fmaxf(mt0, __shfl_xor_sync(0xffffffffu, mt0, 1));
            mt0 = fmaxf(mt0, __shfl_xor_sync(0xffffffffu, mt0, 2));
            mt1 = fmaxf(mt1, __shfl_xor_sync(0xffffffffu, mt1, 1));
            mt1 = fmaxf(mt1, __shfl_xor_sync(0xffffffffu, mt1, 2));
            float mn0 = fmaxf(m0v, mt0), mn1 = fmaxf(m1v, mt1);
            float al0 = ex2(m0v - mn0), al1 = ex2(m1v - mn1);
            m0v = mn0; m1v = mn1; l0v *= al0; l1v *= al1;

            float rs0 = 0.f, rs1 = 0.f;
            #pragma unroll
            for (int nf = 0; nf < 8; nf++) {
                s[nf].x = ex2(s[nf].x - mn0);
                s[nf].y = ex2(s[nf].y - mn0);
                s[nf].z = ex2(s[nf].z - mn1);
                s[nf].w = ex2(s[nf].w - mn1);
                rs0 += s[nf].x + s[nf].y;
                rs1 += s[nf].z + s[nf].w;
                o[nf].x *= al0; o[nf].y *= al0;
                o[nf].z *= al1; o[nf].w *= al1;
            }
            rs0 += __shfl_xor_sync(0xffffffffu, rs0, 1);
            rs0 += __shfl_xor_sync(0xffffffffu, rs0, 2);
            rs1 += __shfl_xor_sync(0xffffffffu, rs1, 1);
            rs1 += __shfl_xor_sync(0xffffffffu, rs1, 2);
            l0v += rs0; l1v += rs1;

            #pragma unroll
            for (int ch = 0; ch < 4; ch++) {
                int n0 = 2 * ch, n1 = n0 + 1;
                uint32_t a0h, a0l, a1h, a1l, a2h, a2l, a3h, a3l;
                psplit(s[n0].x, s[n0].y, a0h, a0l);
                psplit(s[n0].z, s[n0].w, a1h, a1l);
                psplit(s[n1].x, s[n1].y, a2h, a2l);
                psplit(s[n1].z, s[n1].w, a3h, a3l);
                #pragma unroll
                for (int nf = 0; nf < 8; nf++) {
                    uint4 vv = Vp[(nf * 8 + r0) * FQT + ch * 4 + c4];
                    mma16(o[nf], a0h, a1h, a2h, a3h, vv.x, vv.y);
                    mma16(o[nf], a0h, a1h, a2h, a3h, vv.z, vv.w);
                    mma16(o[nf], a0l, a1l, a2l, a3l, vv.x, vv.y);
                }
            }
        }
        buf ^= 1;
    }

    float inv0 = 1.f / l0v, inv1 = 1.f / l1v;
    size_t ro0 = ((size_t)bh * SS + ri0) * 16;
    size_t ro1 = ((size_t)bh * SS + ri1) * 16;
    #pragma unroll
    for (int ch = 0; ch < 4; ch++) {
        g_op[ro0 + ch * 4 + c4] = packsplit(
            o[2*ch].x * inv0, o[2*ch].y * inv0,
            o[2*ch+1].x * inv0, o[2*ch+1].y * inv0);
        g_op[ro1 + ch * 4 + c4] = packsplit(
            o[2*ch].z * inv1, o[2*ch].w * inv1,
            o[2*ch+1].z * inv1, o[2*ch+1].w * inv1);
    }
    if (c4 == 0) {
        g_m[bh * SS + ri0] = m0v; g_m[bh * SS + ri1] = m1v;
        g_l[bh * SS + ri0] = l0v; g_l[bh * SS + ri1] = l1v;
    }

    __threadfence();
    __syncthreads();
    if (tid == 0) {
        atomicExch(&g_flag[fi], 1);
        atomicAdd(&g_cnt[(bh >> 3) * 32 + qt], 1);
    }
}

// ---------------------------------------------------------------------------
// attn materialization (recompute QK^T; base-2; streaming stores)
// ---------------------------------------------------------------------------
__device__ __forceinline__ void k_issue(uint32_t smK, int bh, int kbase, int tid)
{
    #pragma unroll
    for (int i = 0; i < 4; i++) {
        int u = tid + i * 256, row = u >> 4, q = u & 15;
        cp16(smK + (row * FQT + q) * 16,
             g_kp + ((size_t)bh * SS + kbase + row) * 16 + q);
    }
    asm volatile("cp.async.commit_group;");
}

__device__ __forceinline__ void attn_write_dev(float* __restrict__ attn, int idx)
{
    extern __shared__ uint4 sme[];
    const int KB = 64 * FQT;
    uint32_t smb = (uint32_t)__cvta_generic_to_shared(sme);
    const uint4* Kb[2] = { sme, sme + KB };
    uint32_t Ka[2] = { smb, smb + (uint32_t)KB * 16 };

    const int tid = threadIdx.x, lane = tid & 31, w = tid >> 5;
    const int r0 = lane >> 2, c4 = lane & 3;
    const int qt = 31 - (idx >> 4);
    const int bh = idx & 15;
    const int qbase = qt * 128;
    const int wrow = qbase + w * 16;
    const int ri0 = wrow + r0, ri1 = ri0 + 8;
    const size_t arow0 = (size_t)bh * SS + ri0;
    const size_t arow1 = (size_t)bh * SS + ri1;

    if (tid == 0) {
        while (atomicAdd(&g_flag[idx], 0) == 0) __nanosleep(200);
    }
    __syncthreads();
    __threadfence();

    k_issue(Ka[0], bh, 0, tid);

    uint4 qa[4], qb[4];
    {
        size_t q0 = ((size_t)bh * SS + ri0) * 16;
        size_t q1 = ((size_t)bh * SS + ri1) * 16;
        #pragma unroll
        for (int ch = 0; ch < 4; ch++) {
            qa[ch] = g_qp[q0 + ch * 4 + c4];
            qb[ch] = g_qp[q1 + ch * 4 + c4];
        }
    }

    const float mi0 = g_m[bh * SS + ri0], mi1 = g_m[bh * SS + ri1];
    const float il0 = 1.f / g_l[bh * SS + ri0], il1 = 1.f / g_l[bh * SS + ri1];

    int buf = 0;
    const int ktmax = 2 * qt + 1;
    for (int kt = 0; kt <= ktmax; kt++) {
        const int kbase = kt << 6;
        asm volatile("cp.async.wait_group 0;");
        __syncthreads();
        if (kt < ktmax) k_issue(Ka[buf ^ 1], bh, (kt + 1) << 6, tid);

        if (kbase <= wrow + 15) {
            const uint4* Kp = Kb[buf];
            float4 s[8];
            #pragma unroll
            for (int i = 0; i < 8; i++) s[i] = make_float4(0.f, 0.f, 0.f, 0.f);
            #pragma unroll
            for (int ch = 0; ch < 4; ch++) {
                #pragma unroll
                for (int nf = 0; nf < 8; nf++) {
                    uint4 kv = Kp[(nf * 8 + r0) * FQT + ch * 4 + c4];
                    mma16(s[nf], qa[ch].x, qb[ch].x, qa[ch].y, qb[ch].y, kv.x, kv.y);
                    mma16(s[nf], qa[ch].x, qb[ch].x, qa[ch].y, qb[ch].y, kv.z, kv.w);
                    mma16(s[nf], qa[ch].z, qb[ch].z, qa[ch].w, qb[ch].w, kv.x, kv.y);
                }
            }
            if (kbase + 63 > wrow) {
                #pragma unroll
                for (int nf = 0; nf < 8; nf++) {
                    int j0 = kbase + nf * 8 + 2 * c4;
                    if (j0     > ri0) s[nf].x = -INFINITY;
                    if (j0 + 1 > ri0) s[nf].y = -INFINITY;
                    if (j0     > ri1) s[nf].z = -INFINITY;
                    if (j0 + 1 > ri1) s[nf].w = -INFINITY;
                }
            }
            #pragma unroll
            for (int nf = 0; nf < 8; nf++) {
                float2 p0 = make_float2(ex2(s[nf].x - mi0) * il0,
                                        ex2(s[nf].y - mi0) * il0);
                float2 p1 = make_float2(ex2(s[nf].z - mi1) * il1,
                                        ex2(s[nf].w - mi1) * il1);
                unsigned long long u0 = *(unsigned long long*)&p0;
                unsigned long long u1 = *(unsigned long long*)&p1;
                unsigned long long o0 = __shfl_xor_sync(0xffffffffu, u0, 1);
                unsigned long long o1 = __shfl_xor_sync(0xffffffffu, u1, 1);
                if (!(c4 & 1)) {
                    int col = kbase + nf * 8 + 2 * c4;
                    float4 st0, st1;
                    ((unsigned long long*)&st0)[0] = u0;
                    ((unsigned long long*)&st0)[1] = o0;
                    ((unsigned long long*)&st1)[0] = u1;
                    ((unsigned long long*)&st1)[1] = o1;
                    __stcs((float4*)&attn[arow0 * SS + col], st0);
                    __stcs((float4*)&attn[arow1 * SS + col], st1);
                }
            }
        } else {
            if (!(c4 & 1)) {
                float4 z = make_float4(0.f, 0.f, 0.f, 0.f);
                #pragma unroll
                for (int nf = 0; nf < 8; nf++) {
                    int col = kbase + nf * 8 + 2 * c4;
                    __stcs((float4*)&attn[arow0 * SS + col], z);
                    __stcs((float4*)&attn[arow1 * SS + col], z);
                }
            }
        }
        buf ^= 1;
    }
}

// ---------------------------------------------------------------------------
// Mega kernel: [proj | flash+zero interleaved | attn+outproj interleaved]
// ---------------------------------------------------------------------------
__global__ __launch_bounds__(256, 2) void mega(
    float* __restrict__ attn,
    const float* __restrict__ bq, const float* __restrict__ bk,
    const float* __restrict__ bv, const float* __restrict__ bo,
    float* __restrict__ out,
    int nFlash, int nAttn, int nGemm)
{
    const int bid = blockIdx.x;
    const int tid = threadIdx.x;
    const int nProj = 1536;

    if (bid < nProj) {
        // projection block: chunk-major (b-interleaved)
        int cc = bid / 24, r = bid % 24;
        int z = r >> 3, col = r & 7;
        int b = cc & 1, c = cc >> 1;
        int rowBase = (b * 32 + c) * 128;
        int colBase = col * 64;
        const uint4* Ag = g_inp + (size_t)z * NROW * 128;
        const uint4* Wg = g_wp + (size_t)z * 512 * 128;
        if (z == 0)
            gemm_core(Ag, 0, Wg, bq, nullptr, g_qp, 0.125f * LOG2E, 0,
                      rowBase, colBase);
        else if (z == 1)
            gemm_core(Ag, 0, Wg, bk, nullptr, g_kp, 1.f, 0, rowBase, colBase);
        else
            gemm_core(Ag, 0, Wg, bv, nullptr, nullptr, 1.f, 1, rowBase, colBase);
        __threadfence();
        __syncthreads();
        if (tid == 0)
            atomicExch(&g_pflag[z * 512 + (b * HH + col) * 32 + c], 1);
        return;
    }

    if (bid < nProj + nFlash) {
        int fb = bid - nProj;
        if (attn) {
            if (fb & 1) {
                // zero-fill block for the causal upper triangle
                int zi = fb >> 1;
                int zqt = zi >> 4, zbh = zi & 15;
                int z0 = (2 * zqt + 2) * 64;
                int cw = (SS - z0) >> 2;
                if (cw > 0) {
                    float4 z = make_float4(0.f, 0.f, 0.f, 0.f);
                    int zqbase = zqt * 128;
                    for (int r = 0; r < 128; r++) {
                        float* rowp = attn +
                            ((size_t)zbh * SS + zqbase + r) * SS + z0;
                        for (int c = tid; c < cw; c += 256)
                            __stcs((float4*)&rowp[4 * c], z);
                    }
                }
                return;
            }
            flash_dev(fb >> 1);
        } else {
            flash_dev(fb);
        }
        return;
    }

    int idx = bid - nProj - nFlash;
    int aidx = -1, gidx = -1;
    if (nAttn && nGemm) {
        if (idx & 1) gidx = idx >> 1; else aidx = idx >> 1;
    } else if (nAttn) aidx = idx;
    else gidx = idx;

    if (aidx >= 0) {
        attn_write_dev(attn, aidx);
    } else {
        int rowBase = (gidx >> 3) * 128;
        int b = rowBase >> 12, qt = (rowBase & (SS - 1)) >> 7;
        if (tid == 0) {
            while (atomicAdd(&g_cnt[b * 32 + qt], 0) < HH) __nanosleep(200);
        }
        __syncthreads();
        __threadfence();
        gemm_core(g_op, 1, g_wp + 3ull * 512 * 128, bo, out, nullptr, 1.f, 0,
                  rowBase, (gidx & 7) * 64);
    }
}

// ---------------------------------------------------------------------------
extern "C" void kernel_launch(void* const* d_in, const int* in_sizes, int n_in,
                              void* d_out, int out_size)
{
    const float* Q  = (const float*)d_in[0];
    const float* Kx = (const float*)d_in[1];
    const float* V  = (const float*)d_in[2];
    const float* Wq = (const float*)d_in[3];
    const float* bq = (const float*)d_in[4];
    const float* Wk = (const float*)d_in[5];
    const float* bk = (const float*)d_in[6];
    const float* Wv = (const float*)d_in[7];
    const float* bv = (const float*)d_in[8];
    const float* Wo = (const float*)d_in[9];
    const float* bo = (const float*)d_in[10];
    float* out = (float*)d_out;

    const int MEGA_SMEM = 4 * 64 * FQT * 16;   // 81920 (covers all paths)
    cudaFuncSetAttribute(mega, cudaFuncAttributeMaxDynamicSharedMemorySize,
                         MEGA_SMEM);

    packall<<<(3 * NI + 4 * NW + 255) / 256, 256>>>(Q, Kx, V, Wq, Wk, Wv, Wo);

    const long long OUTN = (long long)NROW * DM;
    const long long ATTN = (long long)BB * HH * SS * (long long)SS;
    float* out_ptr = out;
    float* attn_ptr = nullptr;
    if ((long long)out_size == ATTN) { attn_ptr = out; out_ptr = nullptr; }
    else if ((long long)out_size >= OUTN + ATTN) attn_ptr = out + OUTN;

    int nFlash = attn_ptr ? 1024 : 512;
    int nAttn  = attn_ptr ? 512 : 0;
    int nGemm  = out_ptr ? 512 : 0;
    mega<<<1536 + nFlash + nAttn + nGemm, 256, MEGA_SMEM>>>(
        attn_ptr, bq, bk, bv, bo, out_ptr, nFlash, nAttn, nGemm);
}